// round 15
// baseline (speedup 1.0000x reference)
#include <cuda_runtime.h>
#include <cstddef>

#define C_    256
#define HW_   16384
#define B_    32
#define F_    256

#define P_    32
#define RP_   36
#define SPW_  36
#define TPC_  8
#define NB_   64
#define NSLOT_ 3

// Scratch (no allocs allowed)
__device__ float g_part[(size_t)B_ * NB_ * C_];   // 2 MB
__device__ float g_z[B_ * NB_];
// transposed weights: [c][o] layout, coalesced for thread-per-output tail
__device__ float g_w1t[C_ * C_];   // cm1_w^T
__device__ float g_w2t[C_ * C_];   // cm2_w^T
__device__ float g_wat[C_ * F_];   // att_w^T
__device__ float g_wct[C_ * F_];   // center-tap^T

// ---------------------------------------------------------------------------
__device__ __forceinline__ unsigned smem_u32(const void* p) {
    return (unsigned)__cvta_generic_to_shared(p);
}
__device__ __forceinline__ void cp16(unsigned dst, const float* src) {
    asm volatile("cp.async.cg.shared.global [%0], [%1], 16;" :: "r"(dst), "l"(src));
}
__device__ __forceinline__ void cp_commit() {
    asm volatile("cp.async.commit_group;");
}
__device__ __forceinline__ void cp_wait0() {
    asm volatile("cp.async.wait_group 0;");
}
__device__ __forceinline__ void cp_wait1() {
    asm volatile("cp.async.wait_group 1;");
}

// ---------------------------------------------------------------------------
// Pass 1 (structure unchanged — at BW ceiling). Each CTA additionally
// transposes 32 elements of each weight matrix (amortized: one full
// transpose of all four matrices across the 2048-CTA grid, hidden in the
// 512 MB stream). Tail launches strictly after pass1, so no races.
// ---------------------------------------------------------------------------
__global__ __launch_bounds__(256, 2)
void ctx_pass1(const float* __restrict__ x,
               const float* __restrict__ mask_w,
               const float* __restrict__ mask_b,
               const float* __restrict__ cm1_w,
               const float* __restrict__ cm2_w,
               const float* __restrict__ att_w,
               const float* __restrict__ out_w) {
    extern __shared__ float sm[];
    __shared__ float spart[8 * SPW_];
    __shared__ __align__(16) float se[8 * SPW_];

    const int b = blockIdx.y, blk = blockIdx.x, t = threadIdx.x;
    const int w = t >> 5, lane = t & 31;
    const int idx = b * NB_ + blk;
    const float* xb = x + (size_t)b * C_ * HW_ + (size_t)blk * (TPC_ * P_);
    const float mb = mask_b[0];

    // weight transposes: 32 elements of each matrix per CTA
    if (t < 32) {
        int ti = idx * 32 + t;              // 0 .. 65535
        int o = ti >> 8, c = ti & 255;      // consecutive t -> consecutive c
        g_w1t[c * C_ + o] = __ldg(cm1_w + (size_t)o * C_ + c);
        g_w2t[c * C_ + o] = __ldg(cm2_w + (size_t)o * C_ + c);
        g_wat[c * F_ + o] = __ldg(att_w + (size_t)o * C_ + c);
        g_wct[c * F_ + o] = __ldg(out_w + (size_t)o * (C_ * 25) + (size_t)c * 25 + 12);
    }

    float wv[32];
    {
        float myw = mask_w[w * 32 + lane];
#pragma unroll
        for (int cc = 0; cc < 32; cc++)
            wv[cc] = __shfl_sync(0xffffffffu, myw, cc);
    }

    const unsigned smbase = smem_u32(sm);

    auto load_tile = [&](int tile, int slot) {
        const unsigned dbase = smbase + (unsigned)(slot * C_ * RP_) * 4u;
        const float* src0 = xb + tile * P_;
#pragma unroll
        for (int i = 0; i < 8; i++) {
            int s = i * 256 + t;
            int c = s >> 3, q = s & 7;
            cp16(dbase + (unsigned)(c * RP_ + q * 4) * 4u,
                 src0 + (size_t)c * HW_ + q * 4);
        }
    };

    load_tile(0, 0); cp_commit();
    load_tile(1, 1); cp_commit();

    float acc = 0.f;
    float zw  = 0.f;

    int slot = 0;
#pragma unroll 1
    for (int tile = 0; tile < TPC_; tile++) {
        if (tile < TPC_ - 1) cp_wait1();
        else                 cp_wait0();
        __syncthreads();

        if (tile + 2 < TPC_) {
            int ns = slot + 2; if (ns >= NSLOT_) ns -= NSLOT_;
            load_tile(tile + 2, ns);
            cp_commit();
        }

        const float* buf = sm + slot * C_ * RP_;

        float lacc = 0.f;
#pragma unroll
        for (int cc = 0; cc < 32; cc++)
            lacc += buf[(w * 32 + cc) * RP_ + lane] * wv[cc];
        spart[w * SPW_ + lane] = lacc;
        __syncthreads();

        {
            float lg = mb;
#pragma unroll
            for (int g2 = 0; g2 < 8; g2++) lg += spart[g2 * SPW_ + lane];
            float e = __expf(lg);
            se[w * SPW_ + lane] = e;
            if (w == 0) {
                float z = e;
#pragma unroll
                for (int o = 16; o; o >>= 1)
                    z += __shfl_xor_sync(0xffffffffu, z, o);
                zw += z;
            }
            __syncwarp();
        }

        const float4* rowv = reinterpret_cast<const float4*>(buf + t * RP_);
        const float4* sev  = reinterpret_cast<const float4*>(se + w * SPW_);
        float a0 = 0.f, a1 = 0.f;
#pragma unroll
        for (int pp = 0; pp < 8; pp++) {
            float4 xv = rowv[pp], ev = sev[pp];
            a0 += xv.x * ev.x + xv.y * ev.y;
            a1 += xv.z * ev.z + xv.w * ev.w;
        }
        acc += a0 + a1;

        slot++; if (slot >= NSLOT_) slot = 0;
    }

    g_part[(size_t)idx * C_ + t] = acc;
    if (t == 0) g_z[idx] = zw;
}

// ---------------------------------------------------------------------------
// Tail: ONE kernel, grid = B (32 CTAs). Thread t owns output t throughout.
// All weight loads coalesced via the transposed layouts; sv[c] is an smem
// broadcast; no shuffles in the matvecs.
// ---------------------------------------------------------------------------
__global__ __launch_bounds__(256)
void tail_tpo(const float* __restrict__ cm1_b, const float* __restrict__ ln_g,
              const float* __restrict__ ln_b,  const float* __restrict__ cm2_b,
              const float* __restrict__ out_b, const float* __restrict__ att_b,
              float* __restrict__ out) {
    __shared__ float sv[C_];
    __shared__ float sred[20];

    const int b = blockIdx.x, t = threadIdx.x;
    const int w = t >> 5, lane = t & 31;

    // 1/Z
    if (t < 32) {
        float zz = g_z[b * NB_ + t] + g_z[b * NB_ + 32 + t];
#pragma unroll
        for (int o = 16; o; o >>= 1) zz += __shfl_xor_sync(0xffffffffu, zz, o);
        if (t == 0) sred[0] = 1.f / zz;
    }

    // combine partial contexts (thread t = channel t, coalesced over k)
    float acc = 0.f;
    const float* gp = g_part + (size_t)b * NB_ * C_ + t;
#pragma unroll 16
    for (int k = 0; k < NB_; k++) acc += gp[(size_t)k * C_];
    __syncthreads();
    sv[t] = acc * sred[0];
    __syncthreads();

    // h1[t] = cm1_b[t] + sum_c w1t[c][t] * ctx[c]   (coalesced, no shuffles)
    float h;
    {
        float a0 = 0.f, a1 = 0.f, a2 = 0.f, a3 = 0.f;
        const float* wp = g_w1t + t;
#pragma unroll 8
        for (int c = 0; c < C_; c += 4) {
            a0 += wp[(c + 0) * C_] * sv[c + 0];
            a1 += wp[(c + 1) * C_] * sv[c + 1];
            a2 += wp[(c + 2) * C_] * sv[c + 2];
            a3 += wp[(c + 3) * C_] * sv[c + 3];
        }
        h = cm1_b[t] + (a0 + a1) + (a2 + a3);
    }

    // LayerNorm over C + ReLU (block reduce)
    {
        float sum = h, sq = h * h;
#pragma unroll
        for (int o = 16; o; o >>= 1) {
            sum += __shfl_xor_sync(0xffffffffu, sum, o);
            sq  += __shfl_xor_sync(0xffffffffu, sq,  o);
        }
        if (lane == 0) { sred[2 + w] = sum; sred[10 + w] = sq; }
        __syncthreads();
        if (t == 0) {
            float a = 0.f, bb = 0.f;
#pragma unroll
            for (int i = 0; i < 8; i++) { a += sred[2 + i]; bb += sred[10 + i]; }
            sred[0] = a; sred[1] = bb;
        }
        __syncthreads();
        const float mu  = sred[0] * (1.f / C_);
        const float var = sred[1] * (1.f / C_) - mu * mu;
        h = (h - mu) * rsqrtf(var + 1e-5f) * ln_g[t] + ln_b[t];
        h = fmaxf(h, 0.f);
    }
    __syncthreads();
    sv[t] = h;
    __syncthreads();

    // ix[t] = sigmoid(cm2_b[t] + sum_c w2t[c][t] * h[c])
    {
        float a0 = 0.f, a1 = 0.f, a2 = 0.f, a3 = 0.f;
        const float* wp = g_w2t + t;
#pragma unroll 8
        for (int c = 0; c < C_; c += 4) {
            a0 += wp[(c + 0) * C_] * sv[c + 0];
            a1 += wp[(c + 1) * C_] * sv[c + 1];
            a2 += wp[(c + 2) * C_] * sv[c + 2];
            a3 += wp[(c + 3) * C_] * sv[c + 3];
        }
        h = 1.f / (1.f + __expf(-(cm2_b[t] + (a0 + a1) + (a2 + a3))));
    }
    __syncthreads();
    sv[t] = h;
    __syncthreads();

    // gate: thread t = feature t; two dots interleaved (att + center tap)
    {
        float pa0 = 0.f, pa1 = 0.f, pc0 = 0.f, pc1 = 0.f;
        const float* wa = g_wat + t;
        const float* wc = g_wct + t;
#pragma unroll 8
        for (int c = 0; c < C_; c += 2) {
            float v0 = sv[c], v1 = sv[c + 1];
            pa0 += wa[(c + 0) * F_] * v0;
            pc0 += wc[(c + 0) * F_] * v0;
            pa1 += wa[(c + 1) * F_] * v1;
            pc1 += wc[(c + 1) * F_] * v1;
        }
        float av = 1.f / (1.f + __expf(-((pa0 + pa1) + att_b[t])));
        out[b * F_ + t] = av * ((pc0 + pc1) + out_b[t]);
    }
}

extern "C" void kernel_launch(void* const* d_in, const int* in_sizes, int n_in,
                              void* d_out, int out_size) {
    const float* x      = (const float*)d_in[0];
    const float* mask_w = (const float*)d_in[1];
    const float* mask_b = (const float*)d_in[2];
    const float* cm1_w  = (const float*)d_in[3];
    const float* cm1_b  = (const float*)d_in[4];
    const float* ln_g   = (const float*)d_in[5];
    const float* ln_b   = (const float*)d_in[6];
    const float* cm2_w  = (const float*)d_in[7];
    const float* cm2_b  = (const float*)d_in[8];
    const float* out_w  = (const float*)d_in[9];
    const float* out_b  = (const float*)d_in[10];
    const float* att_w  = (const float*)d_in[11];
    const float* att_b  = (const float*)d_in[12];
    float* out = (float*)d_out;

    const int smem1 = NSLOT_ * C_ * RP_ * (int)sizeof(float);  // 110592 B
    cudaFuncSetAttribute(ctx_pass1, cudaFuncAttributeMaxDynamicSharedMemorySize, smem1);

    ctx_pass1<<<dim3(NB_, B_), 256, smem1>>>(x, mask_w, mask_b,
                                             cm1_w, cm2_w, att_w, out_w);
    tail_tpo<<<B_, 256>>>(cm1_b, ln_g, ln_b, cm2_b, out_b, att_b, out);
}

// round 16
// speedup vs baseline: 1.3144x; 1.3144x over previous
#include <cuda_runtime.h>
#include <cstddef>

#define C_    256
#define HW_   16384
#define B_    32
#define F_    256

#define P_    32
#define RP_   36
#define SPW_  36
#define TPC_  8
#define NB_   64
#define NSLOT_ 3

// Scratch (no allocs allowed)
__device__ float g_part[(size_t)B_ * NB_ * C_];   // 2 MB
__device__ float g_z[B_ * NB_];
__device__ float g_wc[F_ * C_];                   // packed center taps
__device__ float g_h1[B_ * C_];
__device__ float g_ix[B_ * C_];
__device__ int   g_cnt0[B_];                      // stage-A arrival counters
__device__ int   g_cnt1[B_];                      // stage-B arrival counters

// ---------------------------------------------------------------------------
__device__ __forceinline__ unsigned smem_u32(const void* p) {
    return (unsigned)__cvta_generic_to_shared(p);
}
__device__ __forceinline__ void cp16(unsigned dst, const float* src) {
    asm volatile("cp.async.cg.shared.global [%0], [%1], 16;" :: "r"(dst), "l"(src));
}
__device__ __forceinline__ void cp_commit() {
    asm volatile("cp.async.commit_group;");
}
__device__ __forceinline__ void cp_wait0() {
    asm volatile("cp.async.wait_group 0;");
}
__device__ __forceinline__ void cp_wait1() {
    asm volatile("cp.async.wait_group 1;");
}

// ---------------------------------------------------------------------------
// Pass 1 (unchanged, at BW ceiling). Additionally: packs center taps AND
// resets the tail's barrier counters (pass1 completes before tail launches,
// so counters are freshly zeroed every replay -> graph-safe determinism).
// ---------------------------------------------------------------------------
__global__ __launch_bounds__(256, 2)
void ctx_pass1(const float* __restrict__ x,
               const float* __restrict__ mask_w,
               const float* __restrict__ mask_b,
               const float* __restrict__ out_w) {
    extern __shared__ float sm[];
    __shared__ float spart[8 * SPW_];
    __shared__ __align__(16) float se[8 * SPW_];

    const int b = blockIdx.y, blk = blockIdx.x, t = threadIdx.x;
    const int w = t >> 5, lane = t & 31;
    const int idx = b * NB_ + blk;
    const float* xb = x + (size_t)b * C_ * HW_ + (size_t)blk * (TPC_ * P_);
    const float mb = mask_b[0];

    if (blk == 0 && t == 0) { g_cnt0[b] = 0; g_cnt1[b] = 0; }

    if (t < 32) {
        int ti = idx * 32 + t;
        int o = ti >> 8, c = ti & 255;
        g_wc[ti] = __ldg(out_w + (size_t)o * (C_ * 25) + (size_t)c * 25 + 12);
    }

    float wv[32];
    {
        float myw = mask_w[w * 32 + lane];
#pragma unroll
        for (int cc = 0; cc < 32; cc++)
            wv[cc] = __shfl_sync(0xffffffffu, myw, cc);
    }

    const unsigned smbase = smem_u32(sm);

    auto load_tile = [&](int tile, int slot) {
        const unsigned dbase = smbase + (unsigned)(slot * C_ * RP_) * 4u;
        const float* src0 = xb + tile * P_;
#pragma unroll
        for (int i = 0; i < 8; i++) {
            int s = i * 256 + t;
            int c = s >> 3, q = s & 7;
            cp16(dbase + (unsigned)(c * RP_ + q * 4) * 4u,
                 src0 + (size_t)c * HW_ + q * 4);
        }
    };

    load_tile(0, 0); cp_commit();
    load_tile(1, 1); cp_commit();

    float acc = 0.f;
    float zw  = 0.f;

    int slot = 0;
#pragma unroll 1
    for (int tile = 0; tile < TPC_; tile++) {
        if (tile < TPC_ - 1) cp_wait1();
        else                 cp_wait0();
        __syncthreads();

        if (tile + 2 < TPC_) {
            int ns = slot + 2; if (ns >= NSLOT_) ns -= NSLOT_;
            load_tile(tile + 2, ns);
            cp_commit();
        }

        const float* buf = sm + slot * C_ * RP_;

        float lacc = 0.f;
#pragma unroll
        for (int cc = 0; cc < 32; cc++)
            lacc += buf[(w * 32 + cc) * RP_ + lane] * wv[cc];
        spart[w * SPW_ + lane] = lacc;
        __syncthreads();

        {
            float lg = mb;
#pragma unroll
            for (int g2 = 0; g2 < 8; g2++) lg += spart[g2 * SPW_ + lane];
            float e = __expf(lg);
            se[w * SPW_ + lane] = e;
            if (w == 0) {
                float z = e;
#pragma unroll
                for (int o = 16; o; o >>= 1)
                    z += __shfl_xor_sync(0xffffffffu, z, o);
                zw += z;
            }
            __syncwarp();
        }

        const float4* rowv = reinterpret_cast<const float4*>(buf + t * RP_);
        const float4* sev  = reinterpret_cast<const float4*>(se + w * SPW_);
        float a0 = 0.f, a1 = 0.f;
#pragma unroll
        for (int pp = 0; pp < 8; pp++) {
            float4 xv = rowv[pp], ev = sev[pp];
            a0 += xv.x * ev.x + xv.y * ev.y;
            a1 += xv.z * ev.z + xv.w * ev.w;
        }
        acc += a0 + a1;

        slot++; if (slot >= NSLOT_) slot = 0;
    }

    g_part[(size_t)idx * C_ + t] = acc;
    if (t == 0) g_z[idx] = zw;
}

// ---------------------------------------------------------------------------
// device barrier among the 4 CTAs of one batch (all co-resident: grid=128)
// ---------------------------------------------------------------------------
__device__ __forceinline__ void batch_barrier(int* cnt, int t) {
    __syncthreads();              // all warps of this CTA done with the stage
    if (t == 0) {
        __threadfence();          // make this CTA's results visible
        atomicAdd(cnt, 1);
        while (atomicAdd(cnt, 0) < 4) {}
    }
    __syncthreads();
    __threadfence();              // order the spin before subsequent reads
}

// ---------------------------------------------------------------------------
// Tail: ONE kernel, grid(4, B) = 128 CTAs. Identical work split to the
// proven 3-kernel version; kernel boundaries replaced by batch barriers.
//   A: combine ctx + 64 rows cm1 -> g_h1        | barrier
//   B: LN(redundant)+ReLU + 64 rows cm2 -> g_ix | barrier
//   C: gate 64 features (att + packed taps)
// ---------------------------------------------------------------------------
__global__ __launch_bounds__(256)
void tail_fused(const float* __restrict__ cm1_w, const float* __restrict__ cm1_b,
                const float* __restrict__ ln_g,  const float* __restrict__ ln_b,
                const float* __restrict__ cm2_w, const float* __restrict__ cm2_b,
                const float* __restrict__ out_b, const float* __restrict__ att_w,
                const float* __restrict__ att_b, float* __restrict__ out) {
    __shared__ float sv[C_];
    __shared__ float sred[20];

    const int b = blockIdx.y, rc = blockIdx.x, t = threadIdx.x;
    const int w = t >> 5, lane = t & 31;

    // ---- Stage A: combine ctx + this CTA's 64 cm1 rows ----
    if (t < 32) {
        float zz = g_z[b * NB_ + t] + g_z[b * NB_ + 32 + t];
#pragma unroll
        for (int o = 16; o; o >>= 1) zz += __shfl_xor_sync(0xffffffffu, zz, o);
        if (t == 0) sred[0] = 1.f / zz;
    }

    float acc = 0.f;
    const float* gp = g_part + (size_t)b * NB_ * C_ + t;
#pragma unroll 8
    for (int k = 0; k < NB_; k++) acc += gp[(size_t)k * C_];
    __syncthreads();
    sv[t] = acc * sred[0];
    __syncthreads();

#pragma unroll
    for (int i = 0; i < 4; i++) {
        int o0 = rc * 64 + w * 8 + 2 * i, o1 = o0 + 1;
        const float* r0 = cm1_w + (size_t)o0 * C_;
        const float* r1 = cm1_w + (size_t)o1 * C_;
        float p0 = 0.f, p1 = 0.f;
#pragma unroll
        for (int j = 0; j < 8; j++) {
            float v = sv[j * 32 + lane];
            p0 += r0[j * 32 + lane] * v;
            p1 += r1[j * 32 + lane] * v;
        }
#pragma unroll
        for (int o = 16; o; o >>= 1) {
            p0 += __shfl_xor_sync(0xffffffffu, p0, o);
            p1 += __shfl_xor_sync(0xffffffffu, p1, o);
        }
        if (lane == 0) {
            g_h1[b * C_ + o0] = p0 + cm1_b[o0];
            g_h1[b * C_ + o1] = p1 + cm1_b[o1];
        }
    }

    batch_barrier(&g_cnt0[b], t);

    // ---- Stage B: LN (redundant per CTA) + ReLU + 64 cm2 rows + sigmoid ----
    float h = g_h1[b * C_ + t];
    {
        float sum = h, sq = h * h;
#pragma unroll
        for (int o = 16; o; o >>= 1) {
            sum += __shfl_xor_sync(0xffffffffu, sum, o);
            sq  += __shfl_xor_sync(0xffffffffu, sq,  o);
        }
        if (lane == 0) { sred[2 + w] = sum; sred[10 + w] = sq; }
        __syncthreads();
        if (t == 0) {
            float a = 0.f, bb = 0.f;
#pragma unroll
            for (int i = 0; i < 8; i++) { a += sred[2 + i]; bb += sred[10 + i]; }
            sred[0] = a; sred[1] = bb;
        }
        __syncthreads();
        const float mu  = sred[0] * (1.f / C_);
        const float var = sred[1] * (1.f / C_) - mu * mu;
        h = (h - mu) * rsqrtf(var + 1e-5f) * ln_g[t] + ln_b[t];
        h = fmaxf(h, 0.f);
    }
    __syncthreads();
    sv[t] = h;
    __syncthreads();

#pragma unroll
    for (int i = 0; i < 4; i++) {
        int o0 = rc * 64 + w * 8 + 2 * i, o1 = o0 + 1;
        const float* r0 = cm2_w + (size_t)o0 * C_;
        const float* r1 = cm2_w + (size_t)o1 * C_;
        float p0 = 0.f, p1 = 0.f;
#pragma unroll
        for (int j = 0; j < 8; j++) {
            float v = sv[j * 32 + lane];
            p0 += r0[j * 32 + lane] * v;
            p1 += r1[j * 32 + lane] * v;
        }
#pragma unroll
        for (int o = 16; o; o >>= 1) {
            p0 += __shfl_xor_sync(0xffffffffu, p0, o);
            p1 += __shfl_xor_sync(0xffffffffu, p1, o);
        }
        if (lane == 0) {
            g_ix[b * C_ + o0] = 1.f / (1.f + __expf(-(p0 + cm2_b[o0])));
            g_ix[b * C_ + o1] = 1.f / (1.f + __expf(-(p1 + cm2_b[o1])));
        }
    }

    batch_barrier(&g_cnt1[b], t);

    // ---- Stage C: gate this CTA's 64 features ----
    sv[t] = g_ix[b * C_ + t];
    __syncthreads();

#pragma unroll
    for (int i = 0; i < 4; i++) {
        int o0 = rc * 64 + w * 8 + 2 * i, o1 = o0 + 1;
        const float* ra0 = att_w + (size_t)o0 * C_;
        const float* ra1 = att_w + (size_t)o1 * C_;
        const float* rc0 = g_wc  + (size_t)o0 * C_;
        const float* rc1 = g_wc  + (size_t)o1 * C_;
        float pa0 = 0.f, pa1 = 0.f, pc0 = 0.f, pc1 = 0.f;
#pragma unroll
        for (int j = 0; j < 8; j++) {
            int c = j * 32 + lane;
            float v = sv[c];
            pa0 += ra0[c] * v;
            pa1 += ra1[c] * v;
            pc0 += rc0[c] * v;
            pc1 += rc1[c] * v;
        }
#pragma unroll
        for (int o = 16; o; o >>= 1) {
            pa0 += __shfl_xor_sync(0xffffffffu, pa0, o);
            pa1 += __shfl_xor_sync(0xffffffffu, pa1, o);
            pc0 += __shfl_xor_sync(0xffffffffu, pc0, o);
            pc1 += __shfl_xor_sync(0xffffffffu, pc1, o);
        }
        if (lane == 0) {
            float a0 = 1.f / (1.f + __expf(-(pa0 + att_b[o0])));
            float a1 = 1.f / (1.f + __expf(-(pa1 + att_b[o1])));
            out[b * F_ + o0] = a0 * (pc0 + out_b[o0]);
            out[b * F_ + o1] = a1 * (pc1 + out_b[o1]);
        }
    }
}

extern "C" void kernel_launch(void* const* d_in, const int* in_sizes, int n_in,
                              void* d_out, int out_size) {
    const float* x      = (const float*)d_in[0];
    const float* mask_w = (const float*)d_in[1];
    const float* mask_b = (const float*)d_in[2];
    const float* cm1_w  = (const float*)d_in[3];
    const float* cm1_b  = (const float*)d_in[4];
    const float* ln_g   = (const float*)d_in[5];
    const float* ln_b   = (const float*)d_in[6];
    const float* cm2_w  = (const float*)d_in[7];
    const float* cm2_b  = (const float*)d_in[8];
    const float* out_w  = (const float*)d_in[9];
    const float* out_b  = (const float*)d_in[10];
    const float* att_w  = (const float*)d_in[11];
    const float* att_b  = (const float*)d_in[12];
    float* out = (float*)d_out;

    const int smem1 = NSLOT_ * C_ * RP_ * (int)sizeof(float);  // 110592 B
    cudaFuncSetAttribute(ctx_pass1, cudaFuncAttributeMaxDynamicSharedMemorySize, smem1);

    ctx_pass1<<<dim3(NB_, B_), 256, smem1>>>(x, mask_w, mask_b, out_w);
    tail_fused<<<dim3(4, B_), 256>>>(cm1_w, cm1_b, ln_g, ln_b, cm2_w, cm2_b,
                                     out_b, att_w, att_b, out);
}